// round 4
// baseline (speedup 1.0000x reference)
#include <cuda_runtime.h>

#define NWIRES  12
#define DIM     4096
#define NLAYERS 4
#define NT      256

typedef unsigned long long u64;

// ---- packed f32x2 helpers (Blackwell dual-fp32 pipe, PTX-only) ----
__device__ __forceinline__ u64 pk2(float lo, float hi) {
    u64 r; asm("mov.b64 %0, {%1,%2};" : "=l"(r) : "f"(lo), "f"(hi)); return r;
}
__device__ __forceinline__ void up2(u64 v, float& lo, float& hi) {
    asm("mov.b64 {%0,%1}, %2;" : "=f"(lo), "=f"(hi) : "l"(v));
}
__device__ __forceinline__ u64 swp(u64 v) {
    float a, b; up2(v, a, b); return pk2(b, a);
}
__device__ __forceinline__ u64 ffma2(u64 a, u64 b, u64 c) {
    u64 d; asm("fma.rn.f32x2 %0, %1, %2, %3;" : "=l"(d) : "l"(a), "l"(b), "l"(c)); return d;
}
__device__ __forceinline__ u64 fmul2(u64 a, u64 b) {
    u64 d; asm("mul.rn.f32x2 %0, %1, %2;" : "=l"(d) : "l"(a), "l"(b)); return d;
}

__device__ __forceinline__ float2 cmul(float2 a, float2 b) {
    return make_float2(fmaf(a.x, b.x, -(a.y * b.y)),
                       fmaf(a.x, b.y,   a.y * b.x));
}
__device__ __forceinline__ float2 cfma(float2 a, float2 b, float2 c) {
    c.x = fmaf(a.x, b.x, fmaf(-a.y, b.y, c.x));
    c.y = fmaf(a.x, b.y, fmaf( a.y, b.x, c.y));
    return c;
}

// bank-conflict-avoiding swizzle: XOR low 4 bits with bits 4-7
__device__ __forceinline__ int saddr(int j) { return j ^ ((j >> 4) & 15); }

// h = g^{-1} (prefix-XOR) of the CNOT-chain permutation, then swizzle
__device__ __forceinline__ int haddr(int j) {
    j ^= j >> 1; j ^= j >> 2; j ^= j >> 4; j ^= j >> 8;
    return saddr(j);
}

// logical index owned by thread t, local slot v, for round R
template <int R>
__device__ __forceinline__ int jidx(int t, int v) {
    if (R == 0) return (t << 4) | v;
    if (R == 1) return ((t & 0xF0) << 4) | (v << 4) | (t & 15);
    return (v << 8) | t;
}

// gather 16 amplitudes; apply the 4 gates of this round in registers (packed)
template <int R>
__device__ __forceinline__ void gather_apply(const u64* __restrict__ st,
                                             const u64* __restrict__ Ugp,
                                             int L, int t, u64* r) {
    #pragma unroll
    for (int v = 0; v < 16; ++v) r[v] = st[saddr(jidx<R>(t, v))];
    #pragma unroll
    for (int lb = 0; lb < 4; ++lb) {
        const int wi = 11 - (4 * R + lb);
        const u64* g = Ugp + (L * NWIRES + wi) * 8;
        const u64 cx00 = g[0], cy00 = g[1], cx01 = g[2], cy01 = g[3];
        const u64 cx10 = g[4], cy10 = g[5], cx11 = g[6], cy11 = g[7];
        const int str = 1 << lb;
        #pragma unroll
        for (int p = 0; p < 8; ++p) {
            const int i0 = ((p & ~(str - 1)) << 1) | (p & (str - 1));
            const int i1 = i0 | str;
            const u64 s0 = r[i0], s1 = r[i1];
            const u64 s0s = swp(s0), s1s = swp(s1);
            r[i0] = ffma2(cx00, s0, ffma2(cy00, s0s, ffma2(cx01, s1, fmul2(cy01, s1s))));
            r[i1] = ffma2(cx10, s0, ffma2(cy10, s0s, ffma2(cx11, s1, fmul2(cy11, s1s))));
        }
    }
}

__global__ __launch_bounds__(NT, 3)
void qnn_kernel(const float* __restrict__ x, const float* __restrict__ w,
                float* __restrict__ out)
{
    __shared__ u64 st[DIM];                          // 32 KB state (swizzled)
    __shared__ u64 Ugp[NLAYERS * NWIRES * 8];        // packed gate constants
    __shared__ float red[8 * 8];

    const int b = blockIdx.x;
    const int t = threadIdx.x;

    // ---- build fused gates U = RZ RY RX @ Enc, store packed (48 threads) ----
    if (t < NLAYERS * NWIRES) {
        const int l = t / NWIRES, wi = t % NWIRES;
        const float* wp = w + (l * NWIRES + wi) * 3;
        float sa, ca, sb, cb, sg, cg;
        sincosf(0.5f * wp[0], &sa, &ca);
        sincosf(0.5f * wp[1], &sb, &cb);
        sincosf(0.5f * wp[2], &sg, &cg);
        float2 m00 = make_float2( cb * ca,  sb * sa);
        float2 m01 = make_float2(-sb * ca, -cb * sa);
        float2 m10 = make_float2( sb * ca, -cb * sa);
        float2 m11 = make_float2( cb * ca, -sb * sa);
        const float2 e0 = make_float2(cg, -sg);
        const float2 e1 = make_float2(cg,  sg);
        m00 = cmul(e0, m00); m01 = cmul(e0, m01);
        m10 = cmul(e1, m10); m11 = cmul(e1, m11);
        const float th = (wi & 1) ? x[b * 2 + 1] : x[b * 2 + 0];
        float se, ce;
        sincosf(0.5f * th, &se, &ce);
        float2 E00, E01, E10, E11;
        if (wi & 1) { // RY
            E00 = make_float2(ce, 0.f);  E01 = make_float2(-se, 0.f);
            E10 = make_float2(se, 0.f);  E11 = make_float2(ce, 0.f);
        } else {      // RX
            E00 = make_float2(ce, 0.f);  E01 = make_float2(0.f, -se);
            E10 = make_float2(0.f, -se); E11 = make_float2(ce, 0.f);
        }
        const float2 u00 = cfma(m01, E10, cmul(m00, E00));
        const float2 u01 = cfma(m01, E11, cmul(m00, E01));
        const float2 u10 = cfma(m11, E10, cmul(m10, E00));
        const float2 u11 = cfma(m11, E11, cmul(m10, E01));
        u64* g = Ugp + t * 8;
        g[0] = pk2(u00.x, u00.x);  g[1] = pk2(-u00.y, u00.y);
        g[2] = pk2(u01.x, u01.x);  g[3] = pk2(-u01.y, u01.y);
        g[4] = pk2(u10.x, u10.x);  g[5] = pk2(-u10.y, u10.y);
        g[6] = pk2(u11.x, u11.x);  g[7] = pk2(-u11.y, u11.y);
    }
    __syncthreads();

    // ---- layer 0 on |0..0>: product state, stored through CNOT map h ----
    {
        u64 pt = pk2(1.f, 0.f);
        #pragma unroll
        for (int bit = 0; bit < 8; ++bit) {
            const u64* g = Ugp + (11 - bit) * 8;
            const int row = (t >> bit) & 1;          // column-0 entry, row = bit val
            pt = ffma2(g[4 * row], pt, fmul2(g[4 * row + 1], swp(pt)));
        }
        #pragma unroll
        for (int v = 0; v < 16; ++v) {
            u64 val = pt;
            #pragma unroll
            for (int bit = 0; bit < 4; ++bit) {
                const u64* g = Ugp + (3 - bit) * 8;
                const int row = (v >> bit) & 1;
                val = ffma2(g[4 * row], val, fmul2(g[4 * row + 1], swp(val)));
            }
            st[haddr((v << 8) | t)] = val;
        }
    }
    __syncthreads();

    u64 r[16];

    // ---- layers 1..2: 3 rounds each, last round scatters through h ----
    for (int L = 1; L <= 2; ++L) {
        gather_apply<0>(st, Ugp, L, t, r);
        #pragma unroll
        for (int v = 0; v < 16; ++v) st[saddr(jidx<0>(t, v))] = r[v];
        __syncthreads();
        gather_apply<1>(st, Ugp, L, t, r);
        #pragma unroll
        for (int v = 0; v < 16; ++v) st[saddr(jidx<1>(t, v))] = r[v];
        __syncthreads();
        gather_apply<2>(st, Ugp, L, t, r);
        #pragma unroll
        for (int v = 0; v < 16; ++v) st[haddr(jidx<2>(t, v))] = r[v];
        __syncthreads();
    }

    // ---- layer 3: rounds 0,1 as usual; round 2 fused with measurement ----
    {
        gather_apply<0>(st, Ugp, 3, t, r);
        #pragma unroll
        for (int v = 0; v < 16; ++v) st[saddr(jidx<0>(t, v))] = r[v];
        __syncthreads();
        gather_apply<1>(st, Ugp, 3, t, r);
        #pragma unroll
        for (int v = 0; v < 16; ++v) st[saddr(jidx<1>(t, v))] = r[v];
        __syncthreads();
        gather_apply<2>(st, Ugp, 3, t, r);
    }

    // ---- measurement straight from registers ----
    float acc0 = 0.f, acc1 = 0.f, acc2 = 0.f, se = 0.f, so = 0.f;
    #pragma unroll
    for (int v = 0; v < 16; ++v) {
        const u64 sq = fmul2(r[v], r[v]);
        float px, py; up2(sq, px, py);
        const float p = px + py;
        const int b3 = (v >> 3) & 1, b2 = (v >> 2) & 1, b1 = (v >> 1) & 1, b0 = v & 1;
        acc0 += b3 ? -p : p;
        acc1 += (b3 ^ b2) ? -p : p;
        acc2 += (b3 ^ b2 ^ b1) ? -p : p;
        if (b3 ^ b2 ^ b1 ^ b0) so += p; else se += p;
    }
    const float d = se - so;
    const int t7 = (t >> 7) & 1, t6 = (t >> 6) & 1, t5 = (t >> 5) & 1, t4 = (t >> 4) & 1;
    float rr[8];
    rr[0] = acc0; rr[1] = acc1; rr[2] = acc2; rr[3] = d;
    rr[4] = t7 ? -d : d;
    rr[5] = (t7 ^ t6) ? -d : d;
    rr[6] = (t7 ^ t6 ^ t5) ? -d : d;
    rr[7] = (t7 ^ t6 ^ t5 ^ t4) ? -d : d;

    const unsigned FULL = 0xffffffffu;
    #pragma unroll
    for (int i = 0; i < 8; ++i) {
        float v = rr[i];
        #pragma unroll
        for (int o = 16; o > 0; o >>= 1) v += __shfl_xor_sync(FULL, v, o);
        if ((t & 31) == 0) red[(t >> 5) * 8 + i] = v;
    }
    __syncthreads();
    if (t < 8) {
        float s = 0.f;
        #pragma unroll
        for (int wp2 = 0; wp2 < 8; ++wp2) s += red[wp2 * 8 + t];
        out[b * 8 + t] = s * 3.14159265358979f;
    }
}

extern "C" void kernel_launch(void* const* d_in, const int* in_sizes, int n_in,
                              void* d_out, int out_size) {
    const float* x = (const float*)d_in[0];   // [B, 2]
    const float* w = (const float*)d_in[1];   // [4, 12, 3]
    float* out = (float*)d_out;               // [B, 8]
    const int B = in_sizes[0] / 2;
    qnn_kernel<<<B, NT>>>(x, w, out);
}

// round 5
// speedup vs baseline: 1.0021x; 1.0021x over previous
#include <cuda_runtime.h>

#define NWIRES  12
#define DIM     4096
#define NLAYERS 4
#define NT      256

__device__ __forceinline__ float2 cmul(float2 a, float2 b) {
    return make_float2(fmaf(a.x, b.x, -(a.y * b.y)),
                       fmaf(a.x, b.y,   a.y * b.x));
}
__device__ __forceinline__ float2 cfma(float2 a, float2 b, float2 c) {
    c.x = fmaf(a.x, b.x, fmaf(-a.y, b.y, c.x));
    c.y = fmaf(a.x, b.y, fmaf( a.y, b.x, c.y));
    return c;
}

// bank-conflict-avoiding swizzle: XOR low 4 bits with bits 4-7
__device__ __forceinline__ int saddr(int j) { return j ^ ((j >> 4) & 15); }

// h = g^{-1} (prefix-XOR) of the CNOT-chain permutation, then swizzle
__device__ __forceinline__ int haddr(int j) {
    j ^= j >> 1; j ^= j >> 2; j ^= j >> 4; j ^= j >> 8;
    return saddr(j);
}

// logical index owned by thread t, local slot v, for round R
template <int R>
__device__ __forceinline__ int jidx(int t, int v) {
    if (R == 0) return (t << 4) | v;
    if (R == 1) return ((t & 0xF0) << 4) | (v << 4) | (t & 15);
    return (v << 8) | t;
}

// gather 16 amplitudes; apply the 4 gates of this round in scalar registers
template <int R>
__device__ __forceinline__ void gather_apply(const float2* __restrict__ st,
                                             const float4* __restrict__ Ug4,
                                             int L, int t,
                                             float* re, float* im) {
    #pragma unroll
    for (int v = 0; v < 16; ++v) {
        const float2 a = st[saddr(jidx<R>(t, v))];
        re[v] = a.x; im[v] = a.y;
    }
    #pragma unroll
    for (int lb = 0; lb < 4; ++lb) {
        const int wi = 11 - (4 * R + lb);
        // g0 = (x00,y00,x01,y01), g1 = (x10,y10,x11,y11)
        const float4 g0 = Ug4[(L * NWIRES + wi) * 2 + 0];
        const float4 g1 = Ug4[(L * NWIRES + wi) * 2 + 1];
        const int str = 1 << lb;
        #pragma unroll
        for (int p = 0; p < 8; ++p) {
            const int i0 = ((p & ~(str - 1)) << 1) | (p & (str - 1));
            const int i1 = i0 | str;
            const float a = re[i0], b = im[i0], c = re[i1], d = im[i1];
            re[i0] = fmaf(g0.x, a, fmaf(-g0.y, b, fmaf(g0.z, c, -g0.w * d)));
            im[i0] = fmaf(g0.y, a, fmaf( g0.x, b, fmaf(g0.w, c,  g0.z * d)));
            re[i1] = fmaf(g1.x, a, fmaf(-g1.y, b, fmaf(g1.z, c, -g1.w * d)));
            im[i1] = fmaf(g1.y, a, fmaf( g1.x, b, fmaf(g1.w, c,  g1.z * d)));
        }
    }
}

__global__ __launch_bounds__(NT, 3)
void qnn_kernel(const float* __restrict__ x, const float* __restrict__ w,
                float* __restrict__ out)
{
    __shared__ float2 st[DIM];                        // 32 KB state (swizzled)
    __shared__ float4 Ug4[NLAYERS * NWIRES * 2];      // gate constants (8 floats/gate)
    __shared__ float  red[8 * 8];

    const int b = blockIdx.x;
    const int t = threadIdx.x;

    // ---- build fused gates U = RZ RY RX @ Enc (48 threads) ----
    if (t < NLAYERS * NWIRES) {
        const int l = t / NWIRES, wi = t % NWIRES;
        const float* wp = w + (l * NWIRES + wi) * 3;
        float sa, ca, sb, cb, sg, cg;
        sincosf(0.5f * wp[0], &sa, &ca);
        sincosf(0.5f * wp[1], &sb, &cb);
        sincosf(0.5f * wp[2], &sg, &cg);
        float2 m00 = make_float2( cb * ca,  sb * sa);
        float2 m01 = make_float2(-sb * ca, -cb * sa);
        float2 m10 = make_float2( sb * ca, -cb * sa);
        float2 m11 = make_float2( cb * ca, -sb * sa);
        const float2 e0 = make_float2(cg, -sg);
        const float2 e1 = make_float2(cg,  sg);
        m00 = cmul(e0, m00); m01 = cmul(e0, m01);
        m10 = cmul(e1, m10); m11 = cmul(e1, m11);
        const float th = (wi & 1) ? x[b * 2 + 1] : x[b * 2 + 0];
        float se, ce;
        sincosf(0.5f * th, &se, &ce);
        float2 E00, E01, E10, E11;
        if (wi & 1) { // RY
            E00 = make_float2(ce, 0.f);  E01 = make_float2(-se, 0.f);
            E10 = make_float2(se, 0.f);  E11 = make_float2(ce, 0.f);
        } else {      // RX
            E00 = make_float2(ce, 0.f);  E01 = make_float2(0.f, -se);
            E10 = make_float2(0.f, -se); E11 = make_float2(ce, 0.f);
        }
        const float2 u00 = cfma(m01, E10, cmul(m00, E00));
        const float2 u01 = cfma(m01, E11, cmul(m00, E01));
        const float2 u10 = cfma(m11, E10, cmul(m10, E00));
        const float2 u11 = cfma(m11, E11, cmul(m10, E01));
        Ug4[t * 2 + 0] = make_float4(u00.x, u00.y, u01.x, u01.y);
        Ug4[t * 2 + 1] = make_float4(u10.x, u10.y, u11.x, u11.y);
    }
    __syncthreads();

    // ---- layer 0 on |0..0>: product state, stored through CNOT map h ----
    {
        float pre = 1.f, pim = 0.f;
        #pragma unroll
        for (int bit = 0; bit < 8; ++bit) {
            const int row = (t >> bit) & 1;
            const float4 g = Ug4[(11 - bit) * 2 + row];   // col-0 entry: (x,y) in .x,.y
            const float nre = fmaf(g.x, pre, -(g.y * pim));
            const float nim = fmaf(g.y, pre,   g.x * pim);
            pre = nre; pim = nim;
        }
        #pragma unroll
        for (int v = 0; v < 16; ++v) {
            float vre = pre, vim = pim;
            #pragma unroll
            for (int bit = 0; bit < 4; ++bit) {
                const int row = (v >> bit) & 1;
                const float4 g = Ug4[(3 - bit) * 2 + row];
                const float nre = fmaf(g.x, vre, -(g.y * vim));
                const float nim = fmaf(g.y, vre,   g.x * vim);
                vre = nre; vim = nim;
            }
            st[haddr((v << 8) | t)] = make_float2(vre, vim);
        }
    }
    __syncthreads();

    float re[16], im[16];

    // ---- layers 1..2: 3 rounds each, last round scatters through h ----
    for (int L = 1; L <= 2; ++L) {
        gather_apply<0>(st, Ug4, L, t, re, im);
        #pragma unroll
        for (int v = 0; v < 16; ++v) st[saddr(jidx<0>(t, v))] = make_float2(re[v], im[v]);
        __syncthreads();
        gather_apply<1>(st, Ug4, L, t, re, im);
        #pragma unroll
        for (int v = 0; v < 16; ++v) st[saddr(jidx<1>(t, v))] = make_float2(re[v], im[v]);
        __syncthreads();
        gather_apply<2>(st, Ug4, L, t, re, im);
        #pragma unroll
        for (int v = 0; v < 16; ++v) st[haddr(jidx<2>(t, v))] = make_float2(re[v], im[v]);
        __syncthreads();
    }

    // ---- layer 3: rounds 0,1 as usual; round 2 fused with measurement ----
    {
        gather_apply<0>(st, Ug4, 3, t, re, im);
        #pragma unroll
        for (int v = 0; v < 16; ++v) st[saddr(jidx<0>(t, v))] = make_float2(re[v], im[v]);
        __syncthreads();
        gather_apply<1>(st, Ug4, 3, t, re, im);
        #pragma unroll
        for (int v = 0; v < 16; ++v) st[saddr(jidx<1>(t, v))] = make_float2(re[v], im[v]);
        __syncthreads();
        gather_apply<2>(st, Ug4, 3, t, re, im);
    }

    // ---- measurement straight from registers ----
    float acc0 = 0.f, acc1 = 0.f, acc2 = 0.f, se = 0.f, so = 0.f;
    #pragma unroll
    for (int v = 0; v < 16; ++v) {
        const float p = fmaf(re[v], re[v], im[v] * im[v]);
        const int b3 = (v >> 3) & 1, b2 = (v >> 2) & 1, b1 = (v >> 1) & 1, b0 = v & 1;
        acc0 += b3 ? -p : p;
        acc1 += (b3 ^ b2) ? -p : p;
        acc2 += (b3 ^ b2 ^ b1) ? -p : p;
        if (b3 ^ b2 ^ b1 ^ b0) so += p; else se += p;
    }
    const float d = se - so;
    const int t7 = (t >> 7) & 1, t6 = (t >> 6) & 1, t5 = (t >> 5) & 1, t4 = (t >> 4) & 1;
    float rr[8];
    rr[0] = acc0; rr[1] = acc1; rr[2] = acc2; rr[3] = d;
    rr[4] = t7 ? -d : d;
    rr[5] = (t7 ^ t6) ? -d : d;
    rr[6] = (t7 ^ t6 ^ t5) ? -d : d;
    rr[7] = (t7 ^ t6 ^ t5 ^ t4) ? -d : d;

    const unsigned FULL = 0xffffffffu;
    #pragma unroll
    for (int i = 0; i < 8; ++i) {
        float v = rr[i];
        #pragma unroll
        for (int o = 16; o > 0; o >>= 1) v += __shfl_xor_sync(FULL, v, o);
        if ((t & 31) == 0) red[(t >> 5) * 8 + i] = v;
    }
    __syncthreads();
    if (t < 8) {
        float s = 0.f;
        #pragma unroll
        for (int wp2 = 0; wp2 < 8; ++wp2) s += red[wp2 * 8 + t];
        out[b * 8 + t] = s * 3.14159265358979f;
    }
}

extern "C" void kernel_launch(void* const* d_in, const int* in_sizes, int n_in,
                              void* d_out, int out_size) {
    const float* x = (const float*)d_in[0];   // [B, 2]
    const float* w = (const float*)d_in[1];   // [4, 12, 3]
    float* out = (float*)d_out;               // [B, 8]
    const int B = in_sizes[0] / 2;
    qnn_kernel<<<B, NT>>>(x, w, out);
}